// round 13
// baseline (speedup 1.0000x reference)
#include <cuda_runtime.h>
#include <cuda_fp16.h>
#include <cstdint>

// ---------------------------------------------------------------------------
// AggregationFusion (sm_103 base-ISA tensor path), LN2 fused away:
//  gather+concat+LN1 (warp/row) -> GEMM1 fp16 HMMA + SiLU -> Hh(fp16)
//     + per-(colTile,warp,row) LN2 partial stats (single-writer, no races)
//  -> stats-reduce kernel -> GEMM2 (A = normalize(Hh) on the fly) + SiLU -> out
// GEMM: 128x128 CTA, BKH=32, NST=3 (61.4KB smem, 2 CTA/SM), m16n8k16.
// ---------------------------------------------------------------------------

#define MAX_N 100000
#define ROWS_PAD 100096          // 782 * 128
#define TWOF  1024
#define FDIM  512
#define LN_EPS 1e-5f

__device__ __half  g_Hh[(size_t)ROWS_PAD * TWOF];  // GEMM1 out (fp16)
__device__ __half  g_Xh[(size_t)ROWS_PAD * TWOF];  // LN1 out (fp16)
__device__ __half  g_Wt1[(size_t)TWOF * TWOF];     // W1^T [n][k]
__device__ __half  g_Wt2[(size_t)FDIM * TWOF];     // W2^T [n][k]
__device__ float2  g_part[32 * (size_t)ROWS_PAD];  // LN2 partial (sum, sumsq)
__device__ float2  g_stats[ROWS_PAD];              // LN2 (mu, rstd)
__device__ int     g_is64;

// ---------------------------------------------------------------------------
__global__ void detect_i64_kernel(const int* __restrict__ comps_words) {
    if (threadIdx.x == 0) {
        int z = 1;
        #pragma unroll
        for (int i = 1; i < 16; i += 2)
            if (comps_words[i] != 0) z = 0;
        g_is64 = z;
    }
}

__device__ __forceinline__ float silu_f(float x) {
    return x * (1.0f / (1.0f + __expf(-x)));
}

// ---------------------------------------------------------------------------
// gather + concat + LN1 (warp per row) -> g_Xh    [R6-proven version]
// ---------------------------------------------------------------------------
__global__ __launch_bounds__(256)
void gather_ln1_kernel(const float* __restrict__ nodes,
                       const void* __restrict__ comps,
                       const float* __restrict__ aggr_nodes,
                       const void* __restrict__ aggr_comps,
                       const float* __restrict__ ln_g,
                       const float* __restrict__ ln_b,
                       int N, int M) {
    int row = blockIdx.x * 8 + (threadIdx.x >> 5);
    if (row >= N) return;
    int lane = threadIdx.x & 31;

    int idx = 0;
    if (lane == 0) {
        int is64 = g_is64;
        long long key = is64 ? ((const long long*)comps)[row]
                             : (long long)((const int*)comps)[row];
        int lo = 0, hi = M;
        while (lo < hi) {
            int mid = (lo + hi) >> 1;
            long long am = is64 ? ((const long long*)aggr_comps)[mid]
                                : (long long)((const int*)aggr_comps)[mid];
            if (am < key) lo = mid + 1; else hi = mid;
        }
        idx = (lo >= M) ? (M - 1) : lo;
    }
    idx = __shfl_sync(0xffffffffu, idx, 0);

    const float4* s1 = (const float4*)(nodes + (size_t)row * FDIM);
    const float4* s2 = (const float4*)(aggr_nodes + (size_t)idx * FDIM);
    float4 v[8];
    #pragma unroll
    for (int i = 0; i < 4; i++) v[i]     = s1[i * 32 + lane];
    #pragma unroll
    for (int i = 0; i < 4; i++) v[4 + i] = s2[i * 32 + lane];

    float sum = 0.0f, sq = 0.0f;
    #pragma unroll
    for (int i = 0; i < 8; i++) {
        sum += v[i].x + v[i].y + v[i].z + v[i].w;
        sq  += v[i].x * v[i].x + v[i].y * v[i].y + v[i].z * v[i].z + v[i].w * v[i].w;
    }
    #pragma unroll
    for (int o = 16; o > 0; o >>= 1) {
        sum += __shfl_xor_sync(0xffffffffu, sum, o);
        sq  += __shfl_xor_sync(0xffffffffu, sq,  o);
    }
    float mu = sum * (1.0f / (float)TWOF);
    float var = sq * (1.0f / (float)TWOF) - mu * mu;
    float rstd = rsqrtf(var + LN_EPS);

    uint2* dst = (uint2*)(g_Xh + (size_t)row * TWOF);
    #pragma unroll
    for (int i = 0; i < 8; i++) {
        int slot = i * 32 + lane;
        float4 gg = ((const float4*)ln_g)[slot];
        float4 bb = ((const float4*)ln_b)[slot];
        __half2 h0 = __floats2half2_rn((v[i].x - mu) * rstd * gg.x + bb.x,
                                       (v[i].y - mu) * rstd * gg.y + bb.y);
        __half2 h1 = __floats2half2_rn((v[i].z - mu) * rstd * gg.z + bb.z,
                                       (v[i].w - mu) * rstd * gg.w + bb.w);
        uint2 p;
        p.x = *(uint32_t*)&h0;
        p.y = *(uint32_t*)&h1;
        dst[slot] = p;
    }
}

// ---------------------------------------------------------------------------
// LN2 stats reduce: 32 partials per row -> (mu, rstd)
// ---------------------------------------------------------------------------
__global__ void ln2_stats_kernel(int N) {
    int row = blockIdx.x * 256 + threadIdx.x;
    if (row >= N) return;
    float s = 0.0f, ss = 0.0f;
    #pragma unroll
    for (int t = 0; t < 32; t++) {
        float2 p = g_part[(size_t)t * ROWS_PAD + row];
        s += p.x; ss += p.y;
    }
    float mu = s * (1.0f / (float)TWOF);
    float var = ss * (1.0f / (float)TWOF) - mu * mu;
    g_stats[row] = make_float2(mu, rsqrtf(var + LN_EPS));
}

// ---------------------------------------------------------------------------
// W transpose + fp16: W[K][Ncols] -> Wt[Ncols][K]
// ---------------------------------------------------------------------------
__global__ void wprep_kernel(const float* __restrict__ W,
                             __half* __restrict__ T,
                             int Ncols) {
    __shared__ float t[32][33];
    int bx = blockIdx.x * 32;   // n
    int by = blockIdx.y * 32;   // k
    int tx = threadIdx.x, ty = threadIdx.y;
    #pragma unroll
    for (int i = 0; i < 32; i += 8)
        t[ty + i][tx] = W[(size_t)(by + ty + i) * Ncols + bx + tx];
    __syncthreads();
    #pragma unroll
    for (int i = 0; i < 32; i += 8) {
        int n = bx + ty + i, k = by + tx;
        T[(size_t)n * TWOF + k] = __float2half_rn(t[tx][ty + i]);
    }
}

// ---------------------------------------------------------------------------
// shared GEMM plumbing
// ---------------------------------------------------------------------------
#define BM 128
#define BN 128
#define BKH 32          // k-halves per stage
#define AST 40          // halves per smem row (32 + 8 pad)
#define NST 3
#define TILE_HALVES (BM * AST)
#define STAGE_BYTES (TILE_HALVES * 2 * 2)      // A + B, bytes (20480)

__device__ __forceinline__ uint32_t smem_u32(const void* p) {
    uint32_t a;
    asm("{ .reg .u64 t; cvta.to.shared.u64 t, %1; cvt.u32.u64 %0, t; }"
        : "=r"(a) : "l"(p));
    return a;
}
__device__ __forceinline__ void ldm_x4(uint32_t& r0, uint32_t& r1,
                                       uint32_t& r2, uint32_t& r3, uint32_t addr) {
    asm volatile("ldmatrix.sync.aligned.m8n8.x4.shared.b16 {%0,%1,%2,%3}, [%4];"
                 : "=r"(r0), "=r"(r1), "=r"(r2), "=r"(r3) : "r"(addr));
}
__device__ __forceinline__ void mma_f16(float& c0, float& c1, float& c2, float& c3,
                                        uint32_t a0, uint32_t a1, uint32_t a2, uint32_t a3,
                                        uint32_t b0, uint32_t b1) {
    asm volatile(
        "mma.sync.aligned.m16n8k16.row.col.f32.f16.f16.f32 "
        "{%0,%1,%2,%3}, {%4,%5,%6,%7}, {%8,%9}, {%0,%1,%2,%3};"
        : "+f"(c0), "+f"(c1), "+f"(c2), "+f"(c3)
        : "r"(a0), "r"(a1), "r"(a2), "r"(a3), "r"(b0), "r"(b1));
}
__device__ __forceinline__ void cp_async16(uint32_t dst, const void* src, unsigned sz) {
    asm volatile("cp.async.cg.shared.global [%0], [%1], 16, %2;\n"
                 :: "r"(dst), "l"(src), "r"(sz));
}
__device__ __forceinline__ void cp_commit() { asm volatile("cp.async.commit_group;\n"); }
__device__ __forceinline__ void cp_wait0()  { asm volatile("cp.async.wait_group 0;\n"); }
__device__ __forceinline__ void cp_wait1()  { asm volatile("cp.async.wait_group 1;\n"); }
__device__ __forceinline__ void sts128(uint32_t addr, uint4 v) {
    asm volatile("st.shared.v4.b32 [%0], {%1,%2,%3,%4};"
                 :: "r"(addr), "r"(v.x), "r"(v.y), "r"(v.z), "r"(v.w));
}

extern __shared__ __half sm_gemm[];

// ---------------------------------------------------------------------------
// GEMM1: Hh = silu(Xh @ W1t^T + b1)  (fp16 out) + LN2 partial stats
// ---------------------------------------------------------------------------
__global__ __launch_bounds__(256, 2)
void gemm1_kernel(const __half* __restrict__ A,
                  const __half* __restrict__ Wt,
                  const float* __restrict__ bias,
                  __half* __restrict__ C,
                  int Nrows) {
    const int K = TWOF, Ncols = TWOF;
    const int KT = K / BKH;       // 32

    __half* AsBase = sm_gemm;
    __half* BsBase = sm_gemm + (size_t)NST * TILE_HALVES;

    int tid = threadIdx.x;
    int lane = tid & 31;
    int wid  = tid >> 5;
    int wm = wid >> 2;
    int wn = wid & 3;
    int rowBase = blockIdx.y * BM;
    int colBase = blockIdx.x * BN;

    int r  = tid >> 1;
    int sg = (tid & 1) * 2;
    int gA = rowBase + r;
    bool a_ok = gA < Nrows;
    unsigned asz = a_ok ? 16u : 0u;
    const char* a_src = (const char*)(A + (size_t)(a_ok ? gA : 0) * K);
    const char* b_src = (const char*)(Wt + (size_t)(colBase + r) * K);
    uint32_t a_dst0 = smem_u32(AsBase + r * AST + sg * 8);
    uint32_t b_dst0 = smem_u32(BsBase + r * AST + sg * 8);
    const uint32_t stB = (uint32_t)(TILE_HALVES * 2);

    auto load_tile = [&](int st, int kt) {
        const char* sa = a_src + kt * (BKH * 2);
        const char* sb = b_src + kt * (BKH * 2);
        uint32_t da = a_dst0 + st * stB;
        uint32_t db = b_dst0 + st * stB;
        #pragma unroll
        for (int i = 0; i < 2; i++) {
            cp_async16(da + i * 16, sa + (sg + i) * 16, asz);
            cp_async16(db + i * 16, sb + (sg + i) * 16, 16u);
        }
        cp_commit();
    };

    int aRow = (lane & 15);
    int aCol = (lane >> 4) * 8;
    int bRow = (lane & 7) + ((lane >> 4) & 1) * 8;
    int bCol = ((lane >> 3) & 1) * 8;

    float acc[4][4][4];
    #pragma unroll
    for (int f = 0; f < 4; f++)
        #pragma unroll
        for (int j = 0; j < 4; j++)
            #pragma unroll
            for (int q = 0; q < 4; q++) acc[f][j][q] = 0.0f;

    load_tile(0, 0);
    load_tile(1, 1);

    for (int kt = 0; kt < KT; kt++) {
        int st = kt % NST;
        if (kt + 1 < KT) cp_wait1(); else cp_wait0();
        __syncthreads();

        if (kt + 2 < KT) load_tile((kt + 2) % NST, kt + 2);

        __half* Asb = AsBase + (size_t)st * TILE_HALVES;
        __half* Bsb = BsBase + (size_t)st * TILE_HALVES;

        #pragma unroll
        for (int ks = 0; ks < 2; ks++) {
            uint32_t a[4][4];
            #pragma unroll
            for (int f = 0; f < 4; f++) {
                uint32_t addr = smem_u32(
                    Asb + (wm * 64 + f * 16 + aRow) * AST + ks * 16 + aCol);
                ldm_x4(a[f][0], a[f][1], a[f][2], a[f][3], addr);
            }
            uint32_t b[4][2];
            #pragma unroll
            for (int jj = 0; jj < 2; jj++) {
                uint32_t addr = smem_u32(
                    Bsb + (wn * 32 + jj * 16 + bRow) * AST + ks * 16 + bCol);
                ldm_x4(b[2 * jj][0], b[2 * jj][1], b[2 * jj + 1][0], b[2 * jj + 1][1], addr);
            }
            #pragma unroll
            for (int f = 0; f < 4; f++)
                #pragma unroll
                for (int j = 0; j < 4; j++)
                    mma_f16(acc[f][j][0], acc[f][j][1], acc[f][j][2], acc[f][j][3],
                            a[f][0], a[f][1], a[f][2], a[f][3], b[j][0], b[j][1]);
        }
    }

    // ---- epilogue: bias + SiLU + store fp16 + LN2 partial stats ----
    // Partial slot = (colTile*4 + wn): exactly one warp writes each slot;
    // within the warp, lane t==0 of each quad row-group writes (no races).
    int g = lane >> 2, t = lane & 3;
    size_t partBase = (size_t)(blockIdx.x * 4 + wn) * ROWS_PAD;
    #pragma unroll
    for (int f = 0; f < 4; f++) {
        int r0 = rowBase + wm * 64 + f * 16 + g;
        int r1 = r0 + 8;
        float s0 = 0.0f, ss0 = 0.0f, s1 = 0.0f, ss1 = 0.0f;
        #pragma unroll
        for (int j = 0; j < 4; j++) {
            int c = colBase + wn * 32 + j * 8 + 2 * t;
            float bv0 = __ldg(&bias[c]), bv1 = __ldg(&bias[c + 1]);
            float x0 = silu_f(acc[f][j][0] + bv0);
            float y0 = silu_f(acc[f][j][1] + bv1);
            float x1 = silu_f(acc[f][j][2] + bv0);
            float y1 = silu_f(acc[f][j][3] + bv1);
            s0 += x0 + y0; ss0 += x0 * x0 + y0 * y0;
            s1 += x1 + y1; ss1 += x1 * x1 + y1 * y1;
            if (r0 < Nrows)
                *(__half2*)(C + (size_t)r0 * Ncols + c) = __floats2half2_rn(x0, y0);
            if (r1 < Nrows)
                *(__half2*)(C + (size_t)r1 * Ncols + c) = __floats2half2_rn(x1, y1);
        }
        // reduce over the 4 quad lanes (t) -> full 32-column partial for this warp
        s0  += __shfl_xor_sync(0xffffffffu, s0, 1);  s0  += __shfl_xor_sync(0xffffffffu, s0, 2);
        ss0 += __shfl_xor_sync(0xffffffffu, ss0, 1); ss0 += __shfl_xor_sync(0xffffffffu, ss0, 2);
        s1  += __shfl_xor_sync(0xffffffffu, s1, 1);  s1  += __shfl_xor_sync(0xffffffffu, s1, 2);
        ss1 += __shfl_xor_sync(0xffffffffu, ss1, 1); ss1 += __shfl_xor_sync(0xffffffffu, ss1, 2);
        if (t == 0) {
            g_part[partBase + r0] = make_float2(s0, ss0);
            g_part[partBase + r1] = make_float2(s1, ss1);
        }
    }
}

// ---------------------------------------------------------------------------
// GEMM2: out = silu(LN2(Hh) @ W2t^T + b2)  (fp32 out)
// A path: LDG(Hh) + fp32 normalize (per-row mu/rstd from g_stats) + STS.
// B path: cp.async 3-stage as before.
// ---------------------------------------------------------------------------
__global__ __launch_bounds__(256, 2)
void gemm2_norm_kernel(const __half* __restrict__ Hh,
                       const float* __restrict__ ln_g,
                       const float* __restrict__ ln_b,
                       const __half* __restrict__ Wt,
                       const float* __restrict__ bias,
                       float* __restrict__ C,
                       int Nrows) {
    const int K = TWOF, Ncols = FDIM;
    const int KT = K / BKH;       // 32

    __half* AsBase = sm_gemm;
    __half* BsBase = sm_gemm + (size_t)NST * TILE_HALVES;

    int tid = threadIdx.x;
    int lane = tid & 31;
    int wid  = tid >> 5;
    int wm = wid >> 2;
    int wn = wid & 3;
    int rowBase = blockIdx.y * BM;
    int colBase = blockIdx.x * BN;

    int r  = tid >> 1;
    int sg = (tid & 1) * 2;      // uint4 index offset within the 4 per kt
    int gA = rowBase + r;
    bool a_ok = gA < Nrows;
    int gAc = a_ok ? gA : 0;
    const uint4* a_src = (const uint4*)(Hh + (size_t)gAc * K);   // 128 uint4/row
    float2 strow = g_stats[gAc];
    float mu = strow.x, rstd = strow.y;

    const char* b_src = (const char*)(Wt + (size_t)(colBase + r) * K);
    uint32_t a_dst0 = smem_u32(AsBase + r * AST + sg * 8);
    uint32_t b_dst0 = smem_u32(BsBase + r * AST + sg * 8);
    const uint32_t stB = (uint32_t)(TILE_HALVES * 2);

    auto loadB = [&](int st, int kt) {
        const char* sb = b_src + kt * (BKH * 2);
        uint32_t db = b_dst0 + st * stB;
        #pragma unroll
        for (int i = 0; i < 2; i++)
            cp_async16(db + i * 16, sb + (sg + i) * 16, 16u);
        cp_commit();
    };

    uint4 rA[2];
    auto ldA = [&](int kt) {
        #pragma unroll
        for (int i = 0; i < 2; i++)
            rA[i] = a_src[kt * 4 + sg + i];
    };
    auto normSTS = [&](int st, int kt) {
        int kbase = kt * BKH + sg * 8;
        uint32_t da = a_dst0 + st * stB;
        #pragma unroll
        for (int i = 0; i < 2; i++) {
            uint4 raw = rA[i];
            const __half2* h = (const __half2*)&raw;
            uint4 o;
            __half2* oh = (__half2*)&o;
            #pragma unroll
            for (int qq = 0; qq < 2; qq++) {
                int k = kbase + i * 8 + qq * 4;
                float4 gg = *(const float4*)(ln_g + k);
                float4 bb = *(const float4*)(ln_b + k);
                float2 p0 = __half22float2(h[qq * 2]);
                float2 p1 = __half22float2(h[qq * 2 + 1]);
                oh[qq * 2]     = __floats2half2_rn((p0.x - mu) * rstd * gg.x + bb.x,
                                                   (p0.y - mu) * rstd * gg.y + bb.y);
                oh[qq * 2 + 1] = __floats2half2_rn((p1.x - mu) * rstd * gg.z + bb.z,
                                                   (p1.y - mu) * rstd * gg.w + bb.w);
            }
            sts128(da + i * 16, o);
        }
    };

    int aRow = (lane & 15);
    int aCol = (lane >> 4) * 8;
    int bRow = (lane & 7) + ((lane >> 4) & 1) * 8;
    int bCol = ((lane >> 3) & 1) * 8;

    float acc[4][4][4];
    #pragma unroll
    for (int f = 0; f < 4; f++)
        #pragma unroll
        for (int j = 0; j < 4; j++)
            #pragma unroll
            for (int q = 0; q < 4; q++) acc[f][j][q] = 0.0f;

    // prologue: A stage 0 via LDG+STS; B stages 0,1 via cp.async
    ldA(0);
    normSTS(0, 0);
    ldA(1);
    loadB(0, 0);
    loadB(1, 1);

    for (int kt = 0; kt < KT; kt++) {
        int st = kt % NST;
        if (kt + 1 < KT) cp_wait1(); else cp_wait0();
        __syncthreads();

        if (kt + 2 < KT) loadB((kt + 2) % NST, kt + 2);
        // A pipeline: STS data for kt+1 (loaded last iteration), then LDG kt+2
        if (kt + 1 < KT) normSTS((kt + 1) % NST, kt + 1);
        if (kt + 2 < KT) ldA(kt + 2);

        __half* Asb = AsBase + (size_t)st * TILE_HALVES;
        __half* Bsb = BsBase + (size_t)st * TILE_HALVES;

        #pragma unroll
        for (int ks = 0; ks < 2; ks++) {
            uint32_t a[4][4];
            #pragma unroll
            for (int f = 0; f < 4; f++) {
                uint32_t addr = smem_u32(
                    Asb + (wm * 64 + f * 16 + aRow) * AST + ks * 16 + aCol);
                ldm_x4(a[f][0], a[f][1], a[f][2], a[f][3], addr);
            }
            uint32_t b[4][2];
            #pragma unroll
            for (int jj = 0; jj < 2; jj++) {
                uint32_t addr = smem_u32(
                    Bsb + (wn * 32 + jj * 16 + bRow) * AST + ks * 16 + bCol);
                ldm_x4(b[2 * jj][0], b[2 * jj][1], b[2 * jj + 1][0], b[2 * jj + 1][1], addr);
            }
            #pragma unroll
            for (int f = 0; f < 4; f++)
                #pragma unroll
                for (int j = 0; j < 4; j++)
                    mma_f16(acc[f][j][0], acc[f][j][1], acc[f][j][2], acc[f][j][3],
                            a[f][0], a[f][1], a[f][2], a[f][3], b[j][0], b[j][1]);
        }
    }

    // ---- epilogue: bias + SiLU + store fp32 ----
    int g = lane >> 2, t = lane & 3;
    #pragma unroll
    for (int f = 0; f < 4; f++) {
        int r0 = rowBase + wm * 64 + f * 16 + g;
        int r1 = r0 + 8;
        #pragma unroll
        for (int j = 0; j < 4; j++) {
            int c = colBase + wn * 32 + j * 8 + 2 * t;
            float bv0 = __ldg(&bias[c]), bv1 = __ldg(&bias[c + 1]);
            if (r0 < Nrows) {
                float2 v;
                v.x = silu_f(acc[f][j][0] + bv0);
                v.y = silu_f(acc[f][j][1] + bv1);
                *(float2*)(C + (size_t)r0 * Ncols + c) = v;
            }
            if (r1 < Nrows) {
                float2 v;
                v.x = silu_f(acc[f][j][2] + bv0);
                v.y = silu_f(acc[f][j][3] + bv1);
                *(float2*)(C + (size_t)r1 * Ncols + c) = v;
            }
        }
    }
}

// ---------------------------------------------------------------------------
extern "C" void kernel_launch(void* const* d_in, const int* in_sizes, int n_in,
                              void* d_out, int out_size) {
    const float* nodes      = (const float*)d_in[1];
    const void*  comps      = d_in[2];
    const float* aggr_nodes = (const float*)d_in[4];
    const void*  aggr_comps = d_in[5];
    const float* ln1_g      = (const float*)d_in[6];
    const float* ln1_b      = (const float*)d_in[7];
    const float* W1         = (const float*)d_in[8];
    const float* b1         = (const float*)d_in[9];
    const float* ln2_g      = (const float*)d_in[10];
    const float* ln2_b      = (const float*)d_in[11];
    const float* W2         = (const float*)d_in[12];
    const float* b2         = (const float*)d_in[13];
    float* out = (float*)d_out;

    int N = in_sizes[1] / FDIM;   // 100000
    int M = in_sizes[4] / FDIM;   // 16384
    if (N > MAX_N) N = MAX_N;

    const int gemm_smem = NST * STAGE_BYTES;   // 61440
    cudaFuncSetAttribute(gemm1_kernel,
                         cudaFuncAttributeMaxDynamicSharedMemorySize, gemm_smem);
    cudaFuncSetAttribute(gemm2_norm_kernel,
                         cudaFuncAttributeMaxDynamicSharedMemorySize, gemm_smem);

    __half *Xh, *Hh, *Wt1, *Wt2;
    cudaGetSymbolAddress((void**)&Xh,  g_Xh);
    cudaGetSymbolAddress((void**)&Hh,  g_Hh);
    cudaGetSymbolAddress((void**)&Wt1, g_Wt1);
    cudaGetSymbolAddress((void**)&Wt2, g_Wt2);

    detect_i64_kernel<<<1, 32>>>((const int*)comps);

    {
        dim3 b(32, 8);
        wprep_kernel<<<dim3(TWOF / 32, TWOF / 32), b>>>(W1, Wt1, TWOF);
        wprep_kernel<<<dim3(FDIM / 32, TWOF / 32), b>>>(W2, Wt2, FDIM);
    }

    gather_ln1_kernel<<<(N + 7) / 8, 256>>>(nodes, comps, aggr_nodes, aggr_comps,
                                            ln1_g, ln1_b, N, M);

    int rowTiles = (N + BM - 1) / BM;
    dim3 grid1(TWOF / BN, rowTiles);
    gemm1_kernel<<<grid1, 256, gemm_smem>>>(Xh, Wt1, b1, Hh, N);

    ln2_stats_kernel<<<(N + 255) / 256, 256>>>(N);

    dim3 grid2(FDIM / BN, rowTiles);
    gemm2_norm_kernel<<<grid2, 256, gemm_smem>>>(Hh, ln2_g, ln2_b, Wt2, b2, out, N);
}

// round 15
// speedup vs baseline: 1.5687x; 1.5687x over previous
#include <cuda_runtime.h>
#include <cuda_fp16.h>
#include <cstdint>

// ---------------------------------------------------------------------------
// AggregationFusion (sm_103 base-ISA tensor path) — R6-proven configuration:
//  gather+concat+LN1 (warp/row) -> GEMM1 fp16 HMMA + SiLU -> H(fp32)
//  -> LN2 (warp/row) -> GEMM2 + SiLU -> out(fp32)
// GEMM: 128x128 CTA, BKH=32, NST=3 (61.4KB smem, 2 CTA/SM), m16n8k16.
// ---------------------------------------------------------------------------

#define MAX_N 100000
#define TWOF  1024
#define FDIM  512
#define LN_EPS 1e-5f

__device__ float   g_H[(size_t)MAX_N * TWOF];      // GEMM1 out (fp32)
__device__ __half  g_Xh[(size_t)MAX_N * TWOF];     // LN1/LN2 out (fp16)
__device__ __half  g_Wt1[(size_t)TWOF * TWOF];     // W1^T [n][k]
__device__ __half  g_Wt2[(size_t)FDIM * TWOF];     // W2^T [n][k]
__device__ int     g_is64;

// ---------------------------------------------------------------------------
__global__ void detect_i64_kernel(const int* __restrict__ comps_words) {
    if (threadIdx.x == 0) {
        int z = 1;
        #pragma unroll
        for (int i = 1; i < 16; i += 2)
            if (comps_words[i] != 0) z = 0;
        g_is64 = z;
    }
}

__device__ __forceinline__ float warp_sum(float v) {
    #pragma unroll
    for (int o = 16; o > 0; o >>= 1) v += __shfl_xor_sync(0xffffffffu, v, o);
    return v;
}

__device__ __forceinline__ float silu_f(float x) {
    return x * (1.0f / (1.0f + __expf(-x)));
}

// ---------------------------------------------------------------------------
// gather + concat + LN1 (warp per row) -> g_Xh   [512 threads = 16 rows/block]
// ---------------------------------------------------------------------------
__global__ __launch_bounds__(512)
void gather_ln1_kernel(const float* __restrict__ nodes,
                       const void* __restrict__ comps,
                       const float* __restrict__ aggr_nodes,
                       const void* __restrict__ aggr_comps,
                       const float* __restrict__ ln_g,
                       const float* __restrict__ ln_b,
                       int N, int M) {
    int row = blockIdx.x * 16 + (threadIdx.x >> 5);
    if (row >= N) return;
    int lane = threadIdx.x & 31;

    int idx = 0;
    if (lane == 0) {
        int is64 = g_is64;
        long long key = is64 ? ((const long long*)comps)[row]
                             : (long long)((const int*)comps)[row];
        int lo = 0, hi = M;
        while (lo < hi) {
            int mid = (lo + hi) >> 1;
            long long am = is64 ? ((const long long*)aggr_comps)[mid]
                                : (long long)((const int*)aggr_comps)[mid];
            if (am < key) lo = mid + 1; else hi = mid;
        }
        idx = (lo >= M) ? (M - 1) : lo;
    }
    idx = __shfl_sync(0xffffffffu, idx, 0);

    const float4* s1 = (const float4*)(nodes + (size_t)row * FDIM);
    const float4* s2 = (const float4*)(aggr_nodes + (size_t)idx * FDIM);
    float4 v[8];
    #pragma unroll
    for (int i = 0; i < 4; i++) v[i]     = s1[i * 32 + lane];
    #pragma unroll
    for (int i = 0; i < 4; i++) v[4 + i] = s2[i * 32 + lane];

    float sum = 0.0f;
    #pragma unroll
    for (int i = 0; i < 8; i++) sum += v[i].x + v[i].y + v[i].z + v[i].w;
    float mu = warp_sum(sum) * (1.0f / (float)TWOF);

    float sq = 0.0f;
    #pragma unroll
    for (int i = 0; i < 8; i++) {
        float a = v[i].x - mu, b = v[i].y - mu, c = v[i].z - mu, d = v[i].w - mu;
        sq += a * a + b * b + c * c + d * d;
    }
    float rstd = rsqrtf(warp_sum(sq) * (1.0f / (float)TWOF) + LN_EPS);

    uint2* dst = (uint2*)(g_Xh + (size_t)row * TWOF);
    #pragma unroll
    for (int i = 0; i < 8; i++) {
        int slot = i * 32 + lane;
        float4 gg = ((const float4*)ln_g)[slot];
        float4 bb = ((const float4*)ln_b)[slot];
        __half2 h0 = __floats2half2_rn((v[i].x - mu) * rstd * gg.x + bb.x,
                                       (v[i].y - mu) * rstd * gg.y + bb.y);
        __half2 h1 = __floats2half2_rn((v[i].z - mu) * rstd * gg.z + bb.z,
                                       (v[i].w - mu) * rstd * gg.w + bb.w);
        uint2 p;
        p.x = *(uint32_t*)&h0;
        p.y = *(uint32_t*)&h1;
        dst[slot] = p;
    }
}

// ---------------------------------------------------------------------------
// LN2 (warp per row) over g_H (fp32) -> g_Xh
// ---------------------------------------------------------------------------
__global__ __launch_bounds__(512)
void ln2_kernel(const float* __restrict__ ln_g,
                const float* __restrict__ ln_b,
                int N) {
    int row = blockIdx.x * 16 + (threadIdx.x >> 5);
    if (row >= N) return;
    int lane = threadIdx.x & 31;

    const float4* src = (const float4*)(g_H + (size_t)row * TWOF);
    float4 v[8];
    #pragma unroll
    for (int i = 0; i < 8; i++) v[i] = src[i * 32 + lane];

    float sum = 0.0f;
    #pragma unroll
    for (int i = 0; i < 8; i++) sum += v[i].x + v[i].y + v[i].z + v[i].w;
    float mu = warp_sum(sum) * (1.0f / (float)TWOF);

    float sq = 0.0f;
    #pragma unroll
    for (int i = 0; i < 8; i++) {
        float a = v[i].x - mu, b = v[i].y - mu, c = v[i].z - mu, d = v[i].w - mu;
        sq += a * a + b * b + c * c + d * d;
    }
    float rstd = rsqrtf(warp_sum(sq) * (1.0f / (float)TWOF) + LN_EPS);

    uint2* dst = (uint2*)(g_Xh + (size_t)row * TWOF);
    #pragma unroll
    for (int i = 0; i < 8; i++) {
        int slot = i * 32 + lane;
        float4 gg = ((const float4*)ln_g)[slot];
        float4 bb = ((const float4*)ln_b)[slot];
        __half2 h0 = __floats2half2_rn((v[i].x - mu) * rstd * gg.x + bb.x,
                                       (v[i].y - mu) * rstd * gg.y + bb.y);
        __half2 h1 = __floats2half2_rn((v[i].z - mu) * rstd * gg.z + bb.z,
                                       (v[i].w - mu) * rstd * gg.w + bb.w);
        uint2 p;
        p.x = *(uint32_t*)&h0;
        p.y = *(uint32_t*)&h1;
        dst[slot] = p;
    }
}

// ---------------------------------------------------------------------------
// W transpose + fp16: W[K][Ncols] -> Wt[Ncols][K]
// ---------------------------------------------------------------------------
__global__ void wprep_kernel(const float* __restrict__ W,
                             __half* __restrict__ T,
                             int Ncols) {
    __shared__ float t[32][33];
    int bx = blockIdx.x * 32;   // n
    int by = blockIdx.y * 32;   // k
    int tx = threadIdx.x, ty = threadIdx.y;
    #pragma unroll
    for (int i = 0; i < 32; i += 8)
        t[ty + i][tx] = W[(size_t)(by + ty + i) * Ncols + bx + tx];
    __syncthreads();
    #pragma unroll
    for (int i = 0; i < 32; i += 8) {
        int n = bx + ty + i, k = by + tx;
        T[(size_t)n * TWOF + k] = __float2half_rn(t[tx][ty + i]);
    }
}

// ---------------------------------------------------------------------------
// fp16 HMMA GEMM, 3-stage cp.async, BKH=32  (R6-measured optimum).
// ---------------------------------------------------------------------------
#define BM 128
#define BN 128
#define BKH 32          // k-halves per stage
#define AST 40          // halves per smem row (32 + 8 pad)
#define NST 3
#define TILE_HALVES (BM * AST)                 // per matrix per stage
#define STAGE_BYTES (TILE_HALVES * 2 * 2)      // A + B, bytes

__device__ __forceinline__ uint32_t smem_u32(const void* p) {
    uint32_t a;
    asm("{ .reg .u64 t; cvta.to.shared.u64 t, %1; cvt.u32.u64 %0, t; }"
        : "=r"(a) : "l"(p));
    return a;
}
__device__ __forceinline__ void ldm_x4(uint32_t& r0, uint32_t& r1,
                                       uint32_t& r2, uint32_t& r3, uint32_t addr) {
    asm volatile("ldmatrix.sync.aligned.m8n8.x4.shared.b16 {%0,%1,%2,%3}, [%4];"
                 : "=r"(r0), "=r"(r1), "=r"(r2), "=r"(r3) : "r"(addr));
}
__device__ __forceinline__ void ldm_x2(uint32_t& r0, uint32_t& r1, uint32_t addr) {
    asm volatile("ldmatrix.sync.aligned.m8n8.x2.shared.b16 {%0,%1}, [%2];"
                 : "=r"(r0), "=r"(r1) : "r"(addr));
}
__device__ __forceinline__ void mma_f16(float& c0, float& c1, float& c2, float& c3,
                                        uint32_t a0, uint32_t a1, uint32_t a2, uint32_t a3,
                                        uint32_t b0, uint32_t b1) {
    asm volatile(
        "mma.sync.aligned.m16n8k16.row.col.f32.f16.f16.f32 "
        "{%0,%1,%2,%3}, {%4,%5,%6,%7}, {%8,%9}, {%0,%1,%2,%3};"
        : "+f"(c0), "+f"(c1), "+f"(c2), "+f"(c3)
        : "r"(a0), "r"(a1), "r"(a2), "r"(a3), "r"(b0), "r"(b1));
}
__device__ __forceinline__ void cp_async16(uint32_t dst, const void* src, unsigned sz) {
    asm volatile("cp.async.cg.shared.global [%0], [%1], 16, %2;\n"
                 :: "r"(dst), "l"(src), "r"(sz));
}
__device__ __forceinline__ void cp_commit() { asm volatile("cp.async.commit_group;\n"); }
__device__ __forceinline__ void cp_wait0()  { asm volatile("cp.async.wait_group 0;\n"); }
__device__ __forceinline__ void cp_wait1()  { asm volatile("cp.async.wait_group 1;\n"); }

extern __shared__ __half sm_gemm[];

__global__ __launch_bounds__(256, 2)
void gemm_f16_bias_silu_kernel(const __half* __restrict__ A,
                               const __half* __restrict__ Wt,
                               const float* __restrict__ bias,
                               float* __restrict__ C,
                               int Nrows, int Ncols) {
    const int K = TWOF;
    const int KT = K / BKH;       // 32

    __half* AsBase = sm_gemm;
    __half* BsBase = sm_gemm + (size_t)NST * TILE_HALVES;

    int tid = threadIdx.x;
    int lane = tid & 31;
    int wid  = tid >> 5;
    int wm = wid >> 2;            // 0..1
    int wn = wid & 3;             // 0..3
    int rowBase = blockIdx.y * BM;
    int colBase = blockIdx.x * BN;

    // cp.async mapping: thread -> row tid>>1, two 16B segs
    int r  = tid >> 1;
    int sg = (tid & 1) * 2;
    int gA = rowBase + r;
    bool a_ok = gA < Nrows;
    unsigned asz = a_ok ? 16u : 0u;
    const char* a_src = (const char*)(A + (size_t)(a_ok ? gA : 0) * K);
    const char* b_src = (const char*)(Wt + (size_t)(colBase + r) * K);
    uint32_t a_dst0 = smem_u32(AsBase + r * AST + sg * 8);
    uint32_t b_dst0 = smem_u32(BsBase + r * AST + sg * 8);
    const uint32_t stB = (uint32_t)(TILE_HALVES * 2);   // bytes per stage per matrix

    auto load_tile = [&](int st, int kt) {
        const char* sa = a_src + kt * (BKH * 2);
        const char* sb = b_src + kt * (BKH * 2);
        uint32_t da = a_dst0 + st * stB;
        uint32_t db = b_dst0 + st * stB;
        #pragma unroll
        for (int i = 0; i < 2; i++) {
            cp_async16(da + i * 16, sa + (sg + i) * 16, asz);
            cp_async16(db + i * 16, sb + (sg + i) * 16, 16u);
        }
        cp_commit();
    };

    int aRow = (lane & 15);
    int aCol = (lane >> 4) * 8;
    int bRow = (lane & 7);
    int bCol = ((lane >> 3) & 1) * 8;

    float acc[4][4][4];
    #pragma unroll
    for (int f = 0; f < 4; f++)
        #pragma unroll
        for (int j = 0; j < 4; j++)
            #pragma unroll
            for (int q = 0; q < 4; q++) acc[f][j][q] = 0.0f;

    load_tile(0, 0);
    load_tile(1, 1);

    for (int kt = 0; kt < KT; kt++) {
        int st = kt % NST;
        if (kt + 1 < KT) cp_wait1(); else cp_wait0();
        __syncthreads();

        if (kt + 2 < KT) load_tile((kt + 2) % NST, kt + 2);

        __half* Asb = AsBase + (size_t)st * TILE_HALVES;
        __half* Bsb = BsBase + (size_t)st * TILE_HALVES;

        #pragma unroll
        for (int ks = 0; ks < 2; ks++) {
            uint32_t a[4][4];
            #pragma unroll
            for (int f = 0; f < 4; f++) {
                uint32_t addr = smem_u32(
                    Asb + (wm * 64 + f * 16 + aRow) * AST + ks * 16 + aCol);
                ldm_x4(a[f][0], a[f][1], a[f][2], a[f][3], addr);
            }
            uint32_t b[4][2];
            #pragma unroll
            for (int j = 0; j < 4; j++) {
                uint32_t addr = smem_u32(
                    Bsb + (wn * 32 + j * 8 + bRow) * AST + ks * 16 + bCol);
                ldm_x2(b[j][0], b[j][1], addr);
            }
            #pragma unroll
            for (int f = 0; f < 4; f++)
                #pragma unroll
                for (int j = 0; j < 4; j++)
                    mma_f16(acc[f][j][0], acc[f][j][1], acc[f][j][2], acc[f][j][3],
                            a[f][0], a[f][1], a[f][2], a[f][3], b[j][0], b[j][1]);
        }
    }

    // ---- epilogue: bias + SiLU + store fp32 ----
    int g = lane >> 2, t = lane & 3;
    #pragma unroll
    for (int f = 0; f < 4; f++) {
        int r0 = rowBase + wm * 64 + f * 16 + g;
        int r1 = r0 + 8;
        #pragma unroll
        for (int j = 0; j < 4; j++) {
            int c = colBase + wn * 32 + j * 8 + 2 * t;
            float bv0 = __ldg(&bias[c]), bv1 = __ldg(&bias[c + 1]);
            if (r0 < Nrows) {
                float2 v;
                v.x = silu_f(acc[f][j][0] + bv0);
                v.y = silu_f(acc[f][j][1] + bv1);
                *(float2*)(C + (size_t)r0 * Ncols + c) = v;
            }
            if (r1 < Nrows) {
                float2 v;
                v.x = silu_f(acc[f][j][2] + bv0);
                v.y = silu_f(acc[f][j][3] + bv1);
                *(float2*)(C + (size_t)r1 * Ncols + c) = v;
            }
        }
    }
}

// ---------------------------------------------------------------------------
extern "C" void kernel_launch(void* const* d_in, const int* in_sizes, int n_in,
                              void* d_out, int out_size) {
    const float* nodes      = (const float*)d_in[1];
    const void*  comps      = d_in[2];
    const float* aggr_nodes = (const float*)d_in[4];
    const void*  aggr_comps = d_in[5];
    const float* ln1_g      = (const float*)d_in[6];
    const float* ln1_b      = (const float*)d_in[7];
    const float* W1         = (const float*)d_in[8];
    const float* b1         = (const float*)d_in[9];
    const float* ln2_g      = (const float*)d_in[10];
    const float* ln2_b      = (const float*)d_in[11];
    const float* W2         = (const float*)d_in[12];
    const float* b2         = (const float*)d_in[13];
    float* out = (float*)d_out;

    int N = in_sizes[1] / FDIM;   // 100000
    int M = in_sizes[4] / FDIM;   // 16384
    if (N > MAX_N) N = MAX_N;

    const int gemm_smem = NST * STAGE_BYTES;   // 61440
    cudaFuncSetAttribute(gemm_f16_bias_silu_kernel,
                         cudaFuncAttributeMaxDynamicSharedMemorySize, gemm_smem);

    __half *Xh, *Wt1, *Wt2;
    float* Hp;
    cudaGetSymbolAddress((void**)&Xh,  g_Xh);
    cudaGetSymbolAddress((void**)&Wt1, g_Wt1);
    cudaGetSymbolAddress((void**)&Wt2, g_Wt2);
    cudaGetSymbolAddress((void**)&Hp,  g_H);

    detect_i64_kernel<<<1, 32>>>((const int*)comps);

    {
        dim3 b(32, 8);
        wprep_kernel<<<dim3(TWOF / 32, TWOF / 32), b>>>(W1, Wt1, TWOF);
        wprep_kernel<<<dim3(FDIM / 32, TWOF / 32), b>>>(W2, Wt2, FDIM);
    }

    gather_ln1_kernel<<<(N + 15) / 16, 512>>>(nodes, comps, aggr_nodes, aggr_comps,
                                              ln1_g, ln1_b, N, M);

    int rowTiles = (N + BM - 1) / BM;
    dim3 grid1(TWOF / BN, rowTiles);
    gemm_f16_bias_silu_kernel<<<grid1, 256, gemm_smem>>>(Xh, Wt1, b1, Hp, N, TWOF);

    ln2_kernel<<<(N + 15) / 16, 512>>>(ln2_g, ln2_b, N);

    dim3 grid2(FDIM / BN, rowTiles);
    gemm_f16_bias_silu_kernel<<<grid2, 256, gemm_smem>>>(Xh, Wt2, b2, out, N, FDIM);
}